// round 8
// baseline (speedup 1.0000x reference)
#include <cuda_runtime.h>
#include <math.h>

#define NB 32
#define NC 256
#define NH 56
#define NW 56
#define NP 49
#define CMID 64
#define NSL 8            // conv1 split-K slices (32 channels each)

typedef unsigned long long ull;

__device__ __forceinline__ void fma2(ull& d, ull a, ull b) {
    asm("fma.rn.f32x2 %0, %1, %2, %0;" : "+l"(d) : "l"(a), "l"(b));
}
__device__ __forceinline__ ull pack2(float a, float b) {
    ull r;
    asm("mov.b64 %0, {%1, %2};" : "=l"(r) : "f"(a), "f"(b));
    return r;
}

// ---------------- scratch ----------------
__device__ float g_pooled[NB * NC * NP];
__device__ float g_w1t[2304 * CMID];            // [k=c*9+t][oc]
__device__ float g_w2d[576 * NC];               // [k=c*9+t][oc] (diff oc - (oc+256))
__device__ float g_b2d[NC];
__device__ float g_c1part[NB * CMID * NP * NSL];
__device__ float g_l2part[NB * NC * NP * 2];    // conv2-diff partials (2 ic-slices)

#define W1N (CMID * 2304)
#define W2DN (NC * 576)
#define WTN (W1N + W2DN + NC)
#define POOLBLKS (NB * NC)
#define WTBLKS ((WTN + 415) / 416)

// ---------------- kernel 0: pool (56x56 -> 7x7)  ||  weight prep ----------------
__global__ void prep_kernel(const float* __restrict__ x, const float* __restrict__ w1,
                            const float* __restrict__ w2, const float* __restrict__ b2) {
    const int tid = threadIdx.x;
    if (blockIdx.x < POOLBLKS) {
        __shared__ float srow[392];
        const int bc = blockIdx.x;
        if (tid < 392) {
            const int r = tid / 7, s = tid % 7;
            const float4* p = reinterpret_cast<const float4*>(
                x + (size_t)bc * (NH * NW) + r * NW + s * 8);
            float4 v0 = p[0], v1 = p[1];
            srow[tid] = (v0.x + v0.y + v0.z + v0.w) + (v1.x + v1.y + v1.z + v1.w);
        }
        __syncthreads();
        if (tid < NP) {
            const int wi = tid / 7, wj = tid % 7;
            float s = 0.f;
#pragma unroll
            for (int k = 0; k < 8; k++) s += srow[(wi * 8 + k) * 7 + wj];
            g_pooled[bc * NP + tid] = s * (1.0f / 64.0f);
        }
    } else {
        const int i = (blockIdx.x - POOLBLKS) * 416 + tid;
        if (i < W1N) {
            int oc = i / 2304, k = i % 2304;
            g_w1t[k * CMID + oc] = w1[i];
        } else if (i < W1N + W2DN) {
            int j = i - W1N;
            int oc = j / 576, k = j % 576;
            g_w2d[k * NC + oc] = w2[oc * 576 + k] - w2[(oc + 256) * 576 + k];
        } else if (i < WTN) {
            int oc = i - W1N - W2DN;
            g_b2d[oc] = b2[oc] - b2[oc + 256];
        }
    }
}

// ---------------- kernel 1: conv1 3x3 (256->64), split-K=8 ----------------
__global__ void __launch_bounds__(224, 2) conv1_kernel() {
    __shared__ float s_act[8 * 108];
    __shared__ float s_w[4608];
    const int sl = blockIdx.x, b = blockIdx.y;
    const int tid = threadIdx.x;
    const int r = tid >> 5, lane = tid & 31;

    float acc0[7], acc1[7];
#pragma unroll
    for (int i = 0; i < 7; i++) { acc0[i] = 0.f; acc1[i] = 0.f; }

    for (int chunk = 0; chunk < 4; chunk++) {
        __syncthreads();
        const int c0 = sl * 32 + chunk * 8;
        for (int idx = tid; idx < 8 * 81; idx += 224) {
            const int c = idx / 81, pp = idx % 81;
            const int pr = pp / 9, pc = pp % 9;
            float v = 0.f;
            if (pr >= 1 && pr <= 7 && pc >= 1 && pc <= 7)
                v = g_pooled[(b * NC + c0 + c) * NP + (pr - 1) * 7 + (pc - 1)];
            s_act[c * 108 + pr * 12 + pc] = v;
        }
        {
            const float4* src = reinterpret_cast<const float4*>(g_w1t + c0 * 9 * CMID);
            float4* dst = reinterpret_cast<float4*>(s_w);
            for (int idx = tid; idx < 1152; idx += 224) dst[idx] = src[idx];
        }
        __syncthreads();

#pragma unroll
        for (int cl = 0; cl < 8; cl++) {
            float aa[3][9];
#pragma unroll
            for (int ti = 0; ti < 3; ti++) {
                const float* rp = s_act + cl * 108 + (r + ti) * 12;
                float4 v0 = *reinterpret_cast<const float4*>(rp);
                float4 v1 = *reinterpret_cast<const float4*>(rp + 4);
                aa[ti][0] = v0.x; aa[ti][1] = v0.y; aa[ti][2] = v0.z; aa[ti][3] = v0.w;
                aa[ti][4] = v1.x; aa[ti][5] = v1.y; aa[ti][6] = v1.z; aa[ti][7] = v1.w;
                aa[ti][8] = rp[8];
            }
#pragma unroll
            for (int ti = 0; ti < 3; ti++) {
#pragma unroll
                for (int tj = 0; tj < 3; tj++) {
                    const float2 w = *reinterpret_cast<const float2*>(
                        s_w + (cl * 9 + ti * 3 + tj) * 64 + lane * 2);
#pragma unroll
                    for (int pj = 0; pj < 7; pj++) {
                        acc0[pj] = fmaf(aa[ti][pj + tj], w.x, acc0[pj]);
                        acc1[pj] = fmaf(aa[ti][pj + tj], w.y, acc1[pj]);
                    }
                }
            }
        }
    }
#pragma unroll
    for (int pj = 0; pj < 7; pj++) {
        const int p = r * 7 + pj;
        g_c1part[((size_t)(b * CMID + lane * 2) * NP + p) * NSL + sl] = acc0[pj];
        g_c1part[((size_t)(b * CMID + lane * 2 + 1) * NP + p) * NSL + sl] = acc1[pj];
    }
}

// ---------------- kernel 2: conv2-diff 3x3 (64->256), fused reduce+BN+GELU ----------------
__global__ void __launch_bounds__(224, 2) conv2_kernel(const float* __restrict__ gamma,
                                                       const float* __restrict__ beta) {
    __shared__ float s_act[8 * 108];
    __shared__ float s_w[4608];
    const int ot = blockIdx.x, ks = blockIdx.y, b = blockIdx.z;
    const int tid = threadIdx.x;
    const int r = tid >> 5, lane = tid & 31;

    float acc0[7], acc1[7];
#pragma unroll
    for (int i = 0; i < 7; i++) { acc0[i] = 0.f; acc1[i] = 0.f; }

    for (int chunk = 0; chunk < 4; chunk++) {
        __syncthreads();
        const int ic0 = ks * 32 + chunk * 8;
        for (int idx = tid; idx < 8 * 81; idx += 224) {
            const int c = idx / 81, pp = idx % 81;
            const int pr = pp / 9, pc = pp % 9;
            float v = 0.f;
            if (pr >= 1 && pr <= 7 && pc >= 1 && pc <= 7) {
                const int mid = ic0 + c;
                const float4* p8 = reinterpret_cast<const float4*>(
                    g_c1part + ((size_t)(b * CMID + mid) * NP + (pr - 1) * 7 + (pc - 1)) * NSL);
                float4 u = p8[0], w4 = p8[1];
                float s = ((u.x + u.y) + (u.z + u.w)) + ((w4.x + w4.y) + (w4.z + w4.w));
                float h = s * (gamma[mid] * rsqrtf(1.0f + 1e-5f)) + beta[mid];
                v = 0.5f * h * (1.0f + erff(h * 0.70710678118654752f));
            }
            s_act[c * 108 + pr * 12 + pc] = v;
        }
        for (int idx = tid; idx < 1152; idx += 224) {
            const int kk = idx >> 4, c4 = idx & 15;
            reinterpret_cast<float4*>(s_w)[idx] = *reinterpret_cast<const float4*>(
                g_w2d + (ic0 * 9 + kk) * NC + ot * 64 + c4 * 4);
        }
        __syncthreads();

#pragma unroll
        for (int cl = 0; cl < 8; cl++) {
            float aa[3][9];
#pragma unroll
            for (int ti = 0; ti < 3; ti++) {
                const float* rp = s_act + cl * 108 + (r + ti) * 12;
                float4 v0 = *reinterpret_cast<const float4*>(rp);
                float4 v1 = *reinterpret_cast<const float4*>(rp + 4);
                aa[ti][0] = v0.x; aa[ti][1] = v0.y; aa[ti][2] = v0.z; aa[ti][3] = v0.w;
                aa[ti][4] = v1.x; aa[ti][5] = v1.y; aa[ti][6] = v1.z; aa[ti][7] = v1.w;
                aa[ti][8] = rp[8];
            }
#pragma unroll
            for (int ti = 0; ti < 3; ti++) {
#pragma unroll
                for (int tj = 0; tj < 3; tj++) {
                    const float2 w = *reinterpret_cast<const float2*>(
                        s_w + (cl * 9 + ti * 3 + tj) * 64 + lane * 2);
#pragma unroll
                    for (int pj = 0; pj < 7; pj++) {
                        acc0[pj] = fmaf(aa[ti][pj + tj], w.x, acc0[pj]);
                        acc1[pj] = fmaf(aa[ti][pj + tj], w.y, acc1[pj]);
                    }
                }
            }
        }
    }

    const int oc0 = ot * 64 + lane * 2;
#pragma unroll
    for (int pj = 0; pj < 7; pj++) {
        const int p = r * 7 + pj;
        g_l2part[((size_t)(b * NC + oc0) * NP + p) * 2 + ks] = acc0[pj];
        g_l2part[((size_t)(b * NC + oc0 + 1) * NP + p) * 2 + ks] = acc1[pj];
    }
}

// ---------------- kernel 3: dw 7x7 depthwise, f32x2 with dual-aligned tiles ----------------
// block 224 = 8 row-groups x 28 col-pairs; thread = 7 rows x 2 cols.
// xs  = 62x62 padded tile (stride 62, rows even*62 -> 8B-aligned pairs at even cols)
// xs1 = xs shifted left by one column (odd-tap pairs become aligned)
// ws2 = 49 pre-packed (w,w) ulls. Zero pack instructions in the hot loop.
__global__ void __launch_bounds__(224, 7) dw_kernel(const float* __restrict__ x,
                                                    const float* __restrict__ wdyn,
                                                    float* __restrict__ y) {
    __shared__ float xs[62 * 62];
    __shared__ float xs1[62 * 62];
    __shared__ ull ws2[49];
    const int bc = blockIdx.x;
    const int tid = threadIdx.x;

    const float* xp = x + (size_t)bc * (NH * NW);
    for (int idx = tid; idx < 62 * 62; idx += 224) {
        const int rr = idx / 62, cc = idx % 62;
        const int gr = rr - 3, gc = cc - 3;
        float v = 0.f;
        if ((unsigned)gr < 56u && (unsigned)gc < 56u) v = xp[gr * 56 + gc];
        xs[idx] = v;
    }
    if (tid < 49) {
        const int c = bc & (NC - 1);
        const float2 lp = *reinterpret_cast<const float2*>(g_l2part + ((size_t)bc * NP + tid) * 2);
        const float ld = lp.x + lp.y + g_b2d[c];
        const float s = 1.0f / (1.0f + expf(-ld));
        const float w0 = wdyn[c * NP + tid];
        const float w1 = wdyn[NC * NP + c * NP + tid];
        const float wv = s * w0 + (1.0f - s) * w1;
        ws2[tid] = pack2(wv, wv);
    }
    __syncthreads();
    // build shifted copy
    for (int idx = tid; idx < 62 * 62; idx += 224) {
        const int cc = idx % 62;
        xs1[idx] = (cc < 61) ? xs[idx + 1] : 0.f;
    }
    __syncthreads();

    const int rg = tid / 28;          // 0..7 -> out rows rg*7 .. rg*7+6
    const int col = (tid % 28) * 2;   // out cols col, col+1

    ull acc[7];
#pragma unroll
    for (int k = 0; k < 7; k++) acc[k] = 0ull;

#pragma unroll
    for (int dj = 0; dj < 7; dj++) {
        const float* base = (dj & 1) ? xs1 : xs;
        const ull* bp = reinterpret_cast<const ull*>(base + rg * 7 * 62 + col + (dj & ~1));
        ull ww[7];
#pragma unroll
        for (int di = 0; di < 7; di++) ww[di] = ws2[di * 7 + dj];
#pragma unroll
        for (int ir = 0; ir < 13; ir++) {
            const ull cv = bp[ir * 31];   // row stride 62 floats = 31 ulls
#pragma unroll
            for (int k = 0; k < 7; k++) {
                const int di = ir - k;
                if (di >= 0 && di < 7) fma2(acc[k], cv, ww[di]);
            }
        }
    }
    float* yp = y + (size_t)bc * (NH * NW);
#pragma unroll
    for (int k = 0; k < 7; k++)
        *reinterpret_cast<ull*>(yp + (rg * 7 + k) * 56 + col) = acc[k];
}

// ---------------- launch ----------------
extern "C" void kernel_launch(void* const* d_in, const int* in_sizes, int n_in,
                              void* d_out, int out_size) {
    const float* x     = (const float*)d_in[0];
    const float* wdyn  = (const float*)d_in[1];
    const float* w1    = (const float*)d_in[2];
    const float* gamma = (const float*)d_in[3];
    const float* beta  = (const float*)d_in[4];
    const float* w2    = (const float*)d_in[5];
    const float* b2    = (const float*)d_in[6];
    float* y = (float*)d_out;

    prep_kernel<<<POOLBLKS + WTBLKS, 416>>>(x, w1, w2, b2);
    conv1_kernel<<<dim3(NSL, NB), 224>>>();
    conv2_kernel<<<dim3(4, 2, NB), 224>>>(gamma, beta);
    dw_kernel<<<NB * NC, 224>>>(x, wdyn, y);
}

// round 9
// speedup vs baseline: 1.3182x; 1.3182x over previous
#include <cuda_runtime.h>
#include <math.h>

#define NB 32
#define NC 256
#define NH 56
#define NW 56
#define NP 49
#define CMID 64
#define NSL 8            // conv1 split-K slices (32 channels each)

typedef unsigned long long ull;

__device__ __forceinline__ void fma2(ull& d, ull a, ull b) {
    asm("fma.rn.f32x2 %0, %1, %2, %0;" : "+l"(d) : "l"(a), "l"(b));
}
__device__ __forceinline__ ull pack2(float a, float b) {
    ull r;
    asm("mov.b64 %0, {%1, %2};" : "=l"(r) : "f"(a), "f"(b));
    return r;
}

// ---------------- scratch ----------------
__device__ float g_pooled[NB * NC * NP];
__device__ float g_w1t[2304 * CMID];            // [k=c*9+t][oc]
__device__ float g_w2d[576 * NC];               // [k=c*9+t][oc] (diff oc - (oc+256))
__device__ float g_b2d[NC];
__device__ float g_c1part[NB * CMID * NP * NSL];
__device__ float g_l2part[NB * NC * NP * 2];    // conv2-diff partials (2 ic-slices)

#define W1N (CMID * 2304)
#define W2DN (NC * 576)
#define WTN (W1N + W2DN + NC)
#define POOLBLKS (NB * NC)
#define WTBLKS ((WTN + 415) / 416)

// ---------------- kernel 0: pool (56x56 -> 7x7)  ||  weight prep ----------------
__global__ void prep_kernel(const float* __restrict__ x, const float* __restrict__ w1,
                            const float* __restrict__ w2, const float* __restrict__ b2) {
    const int tid = threadIdx.x;
    if (blockIdx.x < POOLBLKS) {
        __shared__ float srow[392];
        const int bc = blockIdx.x;
        if (tid < 392) {
            const int r = tid / 7, s = tid % 7;
            const float4* p = reinterpret_cast<const float4*>(
                x + (size_t)bc * (NH * NW) + r * NW + s * 8);
            float4 v0 = p[0], v1 = p[1];
            srow[tid] = (v0.x + v0.y + v0.z + v0.w) + (v1.x + v1.y + v1.z + v1.w);
        }
        __syncthreads();
        if (tid < NP) {
            const int wi = tid / 7, wj = tid % 7;
            float s = 0.f;
#pragma unroll
            for (int k = 0; k < 8; k++) s += srow[(wi * 8 + k) * 7 + wj];
            g_pooled[bc * NP + tid] = s * (1.0f / 64.0f);
        }
    } else {
        const int i = (blockIdx.x - POOLBLKS) * 416 + tid;
        if (i < W1N) {
            int oc = i / 2304, k = i % 2304;
            g_w1t[k * CMID + oc] = w1[i];
        } else if (i < W1N + W2DN) {
            int j = i - W1N;
            int oc = j / 576, k = j % 576;
            g_w2d[k * NC + oc] = w2[oc * 576 + k] - w2[(oc + 256) * 576 + k];
        } else if (i < WTN) {
            int oc = i - W1N - W2DN;
            g_b2d[oc] = b2[oc] - b2[oc + 256];
        }
    }
}

// ---------------- kernel 1: conv1 3x3 (256->64), split-K=8 ----------------
__global__ void __launch_bounds__(224, 2) conv1_kernel() {
    __shared__ float s_act[8 * 108];
    __shared__ float s_w[4608];
    const int sl = blockIdx.x, b = blockIdx.y;
    const int tid = threadIdx.x;
    const int r = tid >> 5, lane = tid & 31;

    float acc0[7], acc1[7];
#pragma unroll
    for (int i = 0; i < 7; i++) { acc0[i] = 0.f; acc1[i] = 0.f; }

    for (int chunk = 0; chunk < 4; chunk++) {
        __syncthreads();
        const int c0 = sl * 32 + chunk * 8;
        for (int idx = tid; idx < 8 * 81; idx += 224) {
            const int c = idx / 81, pp = idx % 81;
            const int pr = pp / 9, pc = pp % 9;
            float v = 0.f;
            if (pr >= 1 && pr <= 7 && pc >= 1 && pc <= 7)
                v = g_pooled[(b * NC + c0 + c) * NP + (pr - 1) * 7 + (pc - 1)];
            s_act[c * 108 + pr * 12 + pc] = v;
        }
        {
            const float4* src = reinterpret_cast<const float4*>(g_w1t + c0 * 9 * CMID);
            float4* dst = reinterpret_cast<float4*>(s_w);
            for (int idx = tid; idx < 1152; idx += 224) dst[idx] = src[idx];
        }
        __syncthreads();

#pragma unroll
        for (int cl = 0; cl < 8; cl++) {
            float aa[3][9];
#pragma unroll
            for (int ti = 0; ti < 3; ti++) {
                const float* rp = s_act + cl * 108 + (r + ti) * 12;
                float4 v0 = *reinterpret_cast<const float4*>(rp);
                float4 v1 = *reinterpret_cast<const float4*>(rp + 4);
                aa[ti][0] = v0.x; aa[ti][1] = v0.y; aa[ti][2] = v0.z; aa[ti][3] = v0.w;
                aa[ti][4] = v1.x; aa[ti][5] = v1.y; aa[ti][6] = v1.z; aa[ti][7] = v1.w;
                aa[ti][8] = rp[8];
            }
#pragma unroll
            for (int ti = 0; ti < 3; ti++) {
#pragma unroll
                for (int tj = 0; tj < 3; tj++) {
                    const float2 w = *reinterpret_cast<const float2*>(
                        s_w + (cl * 9 + ti * 3 + tj) * 64 + lane * 2);
#pragma unroll
                    for (int pj = 0; pj < 7; pj++) {
                        acc0[pj] = fmaf(aa[ti][pj + tj], w.x, acc0[pj]);
                        acc1[pj] = fmaf(aa[ti][pj + tj], w.y, acc1[pj]);
                    }
                }
            }
        }
    }
#pragma unroll
    for (int pj = 0; pj < 7; pj++) {
        const int p = r * 7 + pj;
        g_c1part[((size_t)(b * CMID + lane * 2) * NP + p) * NSL + sl] = acc0[pj];
        g_c1part[((size_t)(b * CMID + lane * 2 + 1) * NP + p) * NSL + sl] = acc1[pj];
    }
}

// ---------------- kernel 2: conv2-diff 3x3 (64->256), fused reduce+BN+GELU ----------------
__global__ void __launch_bounds__(224, 2) conv2_kernel(const float* __restrict__ gamma,
                                                       const float* __restrict__ beta) {
    __shared__ float s_act[8 * 108];
    __shared__ float s_w[4608];
    const int ot = blockIdx.x, ks = blockIdx.y, b = blockIdx.z;
    const int tid = threadIdx.x;
    const int r = tid >> 5, lane = tid & 31;

    float acc0[7], acc1[7];
#pragma unroll
    for (int i = 0; i < 7; i++) { acc0[i] = 0.f; acc1[i] = 0.f; }

    for (int chunk = 0; chunk < 4; chunk++) {
        __syncthreads();
        const int ic0 = ks * 32 + chunk * 8;
        for (int idx = tid; idx < 8 * 81; idx += 224) {
            const int c = idx / 81, pp = idx % 81;
            const int pr = pp / 9, pc = pp % 9;
            float v = 0.f;
            if (pr >= 1 && pr <= 7 && pc >= 1 && pc <= 7) {
                const int mid = ic0 + c;
                const float4* p8 = reinterpret_cast<const float4*>(
                    g_c1part + ((size_t)(b * CMID + mid) * NP + (pr - 1) * 7 + (pc - 1)) * NSL);
                float4 u = p8[0], w4 = p8[1];
                float s = ((u.x + u.y) + (u.z + u.w)) + ((w4.x + w4.y) + (w4.z + w4.w));
                float h = s * (gamma[mid] * rsqrtf(1.0f + 1e-5f)) + beta[mid];
                v = 0.5f * h * (1.0f + erff(h * 0.70710678118654752f));
            }
            s_act[c * 108 + pr * 12 + pc] = v;
        }
        for (int idx = tid; idx < 1152; idx += 224) {
            const int kk = idx >> 4, c4 = idx & 15;
            reinterpret_cast<float4*>(s_w)[idx] = *reinterpret_cast<const float4*>(
                g_w2d + (ic0 * 9 + kk) * NC + ot * 64 + c4 * 4);
        }
        __syncthreads();

#pragma unroll
        for (int cl = 0; cl < 8; cl++) {
            float aa[3][9];
#pragma unroll
            for (int ti = 0; ti < 3; ti++) {
                const float* rp = s_act + cl * 108 + (r + ti) * 12;
                float4 v0 = *reinterpret_cast<const float4*>(rp);
                float4 v1 = *reinterpret_cast<const float4*>(rp + 4);
                aa[ti][0] = v0.x; aa[ti][1] = v0.y; aa[ti][2] = v0.z; aa[ti][3] = v0.w;
                aa[ti][4] = v1.x; aa[ti][5] = v1.y; aa[ti][6] = v1.z; aa[ti][7] = v1.w;
                aa[ti][8] = rp[8];
            }
#pragma unroll
            for (int ti = 0; ti < 3; ti++) {
#pragma unroll
                for (int tj = 0; tj < 3; tj++) {
                    const float2 w = *reinterpret_cast<const float2*>(
                        s_w + (cl * 9 + ti * 3 + tj) * 64 + lane * 2);
#pragma unroll
                    for (int pj = 0; pj < 7; pj++) {
                        acc0[pj] = fmaf(aa[ti][pj + tj], w.x, acc0[pj]);
                        acc1[pj] = fmaf(aa[ti][pj + tj], w.y, acc1[pj]);
                    }
                }
            }
        }
    }

    const int oc0 = ot * 64 + lane * 2;
#pragma unroll
    for (int pj = 0; pj < 7; pj++) {
        const int p = r * 7 + pj;
        g_l2part[((size_t)(b * NC + oc0) * NP + p) * 2 + ks] = acc0[pj];
        g_l2part[((size_t)(b * NC + oc0 + 1) * NP + p) * 2 + ks] = acc1[pj];
    }
}

// ---------------- kernel 3: dw 7x7 depthwise, f32x2 dual-aligned tiles ----------------
// block 224 = 8 row-groups x 28 col-pairs; thread = 7 rows x 2 cols.
// xs  = 62x62 tile; xs1 = xs shifted one column (both built in the load loop).
// ws2 = 49 pre-packed (w,w). launch_bounds(224,6): reg cap 48 -> NO spills (R8 fix).
__global__ void __launch_bounds__(224, 6) dw_kernel(const float* __restrict__ x,
                                                    const float* __restrict__ wdyn,
                                                    float* __restrict__ y) {
    __shared__ float xs[62 * 62];
    __shared__ float xs1[62 * 62];
    __shared__ ull ws2[49];
    const int bc = blockIdx.x;
    const int tid = threadIdx.x;

    const float* xp = x + (size_t)bc * (NH * NW);
    for (int idx = tid; idx < 62 * 62; idx += 224) {
        const int rr = idx / 62, cc = idx % 62;
        const int gr = rr - 3, gc = cc - 3;
        float v = 0.f;
        if ((unsigned)gr < 56u && (unsigned)gc < 56u) v = xp[gr * 56 + gc];
        xs[idx] = v;
        if (cc > 0) xs1[idx - 1] = v;
        if (cc == 61) xs1[idx] = 0.f;
    }
    if (tid < 49) {
        const int c = bc & (NC - 1);
        const float2 lp = *reinterpret_cast<const float2*>(g_l2part + ((size_t)bc * NP + tid) * 2);
        const float ld = lp.x + lp.y + g_b2d[c];
        const float s = 1.0f / (1.0f + expf(-ld));
        const float w0 = wdyn[c * NP + tid];
        const float w1 = wdyn[NC * NP + c * NP + tid];
        const float wv = s * w0 + (1.0f - s) * w1;
        ws2[tid] = pack2(wv, wv);
    }
    __syncthreads();

    const int rg = tid / 28;          // 0..7 -> out rows rg*7 .. rg*7+6
    const int col = (tid % 28) * 2;   // out cols col, col+1

    ull acc[7];
#pragma unroll
    for (int k = 0; k < 7; k++) acc[k] = 0ull;

#pragma unroll
    for (int dj = 0; dj < 7; dj++) {
        const float* base = (dj & 1) ? xs1 : xs;
        const ull* bp = reinterpret_cast<const ull*>(base + rg * 7 * 62 + col + (dj & ~1));
        ull ww[7];
#pragma unroll
        for (int di = 0; di < 7; di++) ww[di] = ws2[di * 7 + dj];
#pragma unroll
        for (int ir = 0; ir < 13; ir++) {
            const ull cv = bp[ir * 31];   // row stride 62 floats = 31 ulls
#pragma unroll
            for (int k = 0; k < 7; k++) {
                const int di = ir - k;
                if (di >= 0 && di < 7) fma2(acc[k], cv, ww[di]);
            }
        }
    }
    float* yp = y + (size_t)bc * (NH * NW);
#pragma unroll
    for (int k = 0; k < 7; k++)
        *reinterpret_cast<ull*>(yp + (rg * 7 + k) * 56 + col) = acc[k];
}

// ---------------- launch ----------------
extern "C" void kernel_launch(void* const* d_in, const int* in_sizes, int n_in,
                              void* d_out, int out_size) {
    const float* x     = (const float*)d_in[0];
    const float* wdyn  = (const float*)d_in[1];
    const float* w1    = (const float*)d_in[2];
    const float* gamma = (const float*)d_in[3];
    const float* beta  = (const float*)d_in[4];
    const float* w2    = (const float*)d_in[5];
    const float* b2    = (const float*)d_in[6];
    float* y = (float*)d_out;

    prep_kernel<<<POOLBLKS + WTBLKS, 416>>>(x, w1, w2, b2);
    conv1_kernel<<<dim3(NSL, NB), 224>>>();
    conv2_kernel<<<dim3(4, 2, NB), 224>>>(gamma, beta);
    dw_kernel<<<NB * NC, 224>>>(x, wdyn, y);
}

// round 10
// speedup vs baseline: 1.5607x; 1.1840x over previous
#include <cuda_runtime.h>
#include <math.h>

#define NB 32
#define NC 256
#define NH 56
#define NW 56
#define NP 49
#define CMID 64
#define NSL 8            // conv1 split-K slices (32 channels each)

// ---------------- scratch ----------------
__device__ float g_pooled[NB * NC * NP];
__device__ float g_w1t[2304 * CMID];            // [k=c*9+t][oc]
__device__ float g_w2d[576 * NC];               // [k=c*9+t][oc] (diff oc - (oc+256))
__device__ float g_b2d[NC];
__device__ float g_c1part[NB * CMID * NP * NSL];
__device__ float g_l2part[NB * NC * NP * 2];    // conv2-diff partials (2 ic-slices)

#define W1N (CMID * 2304)
#define W2DN (NC * 576)
#define WTN (W1N + W2DN + NC)
#define POOLBLKS (NB * NC)
#define WTBLKS ((WTN + 415) / 416)

// ---------------- kernel 0: pool (56x56 -> 7x7)  ||  weight prep ----------------
__global__ void prep_kernel(const float* __restrict__ x, const float* __restrict__ w1,
                            const float* __restrict__ w2, const float* __restrict__ b2) {
    const int tid = threadIdx.x;
    if (blockIdx.x < POOLBLKS) {
        __shared__ float srow[392];
        const int bc = blockIdx.x;
        if (tid < 392) {
            const int r = tid / 7, s = tid % 7;
            const float4* p = reinterpret_cast<const float4*>(
                x + (size_t)bc * (NH * NW) + r * NW + s * 8);
            float4 v0 = p[0], v1 = p[1];
            srow[tid] = (v0.x + v0.y + v0.z + v0.w) + (v1.x + v1.y + v1.z + v1.w);
        }
        __syncthreads();
        if (tid < NP) {
            const int wi = tid / 7, wj = tid % 7;
            float s = 0.f;
#pragma unroll
            for (int k = 0; k < 8; k++) s += srow[(wi * 8 + k) * 7 + wj];
            g_pooled[bc * NP + tid] = s * (1.0f / 64.0f);
        }
    } else {
        const int i = (blockIdx.x - POOLBLKS) * 416 + tid;
        if (i < W1N) {
            int oc = i / 2304, k = i % 2304;
            g_w1t[k * CMID + oc] = w1[i];
        } else if (i < W1N + W2DN) {
            int j = i - W1N;
            int oc = j / 576, k = j % 576;
            g_w2d[k * NC + oc] = w2[oc * 576 + k] - w2[(oc + 256) * 576 + k];
        } else if (i < WTN) {
            int oc = i - W1N - W2DN;
            g_b2d[oc] = b2[oc] - b2[oc + 256];
        }
    }
}

// ---------------- kernel 1: conv1 3x3 (256->64), split-K=8 ----------------
__global__ void __launch_bounds__(224, 2) conv1_kernel() {
    __shared__ float s_act[8 * 108];
    __shared__ float s_w[4608];
    const int sl = blockIdx.x, b = blockIdx.y;
    const int tid = threadIdx.x;
    const int r = tid >> 5, lane = tid & 31;

    float acc0[7], acc1[7];
#pragma unroll
    for (int i = 0; i < 7; i++) { acc0[i] = 0.f; acc1[i] = 0.f; }

    for (int chunk = 0; chunk < 4; chunk++) {
        __syncthreads();
        const int c0 = sl * 32 + chunk * 8;
        for (int idx = tid; idx < 8 * 81; idx += 224) {
            const int c = idx / 81, pp = idx % 81;
            const int pr = pp / 9, pc = pp % 9;
            float v = 0.f;
            if (pr >= 1 && pr <= 7 && pc >= 1 && pc <= 7)
                v = g_pooled[(b * NC + c0 + c) * NP + (pr - 1) * 7 + (pc - 1)];
            s_act[c * 108 + pr * 12 + pc] = v;
        }
        {
            const float4* src = reinterpret_cast<const float4*>(g_w1t + c0 * 9 * CMID);
            float4* dst = reinterpret_cast<float4*>(s_w);
            for (int idx = tid; idx < 1152; idx += 224) dst[idx] = src[idx];
        }
        __syncthreads();

#pragma unroll
        for (int cl = 0; cl < 8; cl++) {
            float aa[3][9];
#pragma unroll
            for (int ti = 0; ti < 3; ti++) {
                const float* rp = s_act + cl * 108 + (r + ti) * 12;
                float4 v0 = *reinterpret_cast<const float4*>(rp);
                float4 v1 = *reinterpret_cast<const float4*>(rp + 4);
                aa[ti][0] = v0.x; aa[ti][1] = v0.y; aa[ti][2] = v0.z; aa[ti][3] = v0.w;
                aa[ti][4] = v1.x; aa[ti][5] = v1.y; aa[ti][6] = v1.z; aa[ti][7] = v1.w;
                aa[ti][8] = rp[8];
            }
#pragma unroll
            for (int ti = 0; ti < 3; ti++) {
#pragma unroll
                for (int tj = 0; tj < 3; tj++) {
                    const float2 w = *reinterpret_cast<const float2*>(
                        s_w + (cl * 9 + ti * 3 + tj) * 64 + lane * 2);
#pragma unroll
                    for (int pj = 0; pj < 7; pj++) {
                        acc0[pj] = fmaf(aa[ti][pj + tj], w.x, acc0[pj]);
                        acc1[pj] = fmaf(aa[ti][pj + tj], w.y, acc1[pj]);
                    }
                }
            }
        }
    }
#pragma unroll
    for (int pj = 0; pj < 7; pj++) {
        const int p = r * 7 + pj;
        g_c1part[((size_t)(b * CMID + lane * 2) * NP + p) * NSL + sl] = acc0[pj];
        g_c1part[((size_t)(b * CMID + lane * 2 + 1) * NP + p) * NSL + sl] = acc1[pj];
    }
}

// ---------------- kernel 2: conv2-diff 3x3 (64->256), fused reduce+BN+GELU ----------------
__global__ void __launch_bounds__(224, 2) conv2_kernel(const float* __restrict__ gamma,
                                                       const float* __restrict__ beta) {
    __shared__ float s_act[8 * 108];
    __shared__ float s_w[4608];
    const int ot = blockIdx.x, ks = blockIdx.y, b = blockIdx.z;
    const int tid = threadIdx.x;
    const int r = tid >> 5, lane = tid & 31;

    float acc0[7], acc1[7];
#pragma unroll
    for (int i = 0; i < 7; i++) { acc0[i] = 0.f; acc1[i] = 0.f; }

    for (int chunk = 0; chunk < 4; chunk++) {
        __syncthreads();
        const int ic0 = ks * 32 + chunk * 8;
        for (int idx = tid; idx < 8 * 81; idx += 224) {
            const int c = idx / 81, pp = idx % 81;
            const int pr = pp / 9, pc = pp % 9;
            float v = 0.f;
            if (pr >= 1 && pr <= 7 && pc >= 1 && pc <= 7) {
                const int mid = ic0 + c;
                const float4* p8 = reinterpret_cast<const float4*>(
                    g_c1part + ((size_t)(b * CMID + mid) * NP + (pr - 1) * 7 + (pc - 1)) * NSL);
                float4 u = p8[0], w4 = p8[1];
                float s = ((u.x + u.y) + (u.z + u.w)) + ((w4.x + w4.y) + (w4.z + w4.w));
                float h = s * (gamma[mid] * rsqrtf(1.0f + 1e-5f)) + beta[mid];
                v = 0.5f * h * (1.0f + erff(h * 0.70710678118654752f));
            }
            s_act[c * 108 + pr * 12 + pc] = v;
        }
        for (int idx = tid; idx < 1152; idx += 224) {
            const int kk = idx >> 4, c4 = idx & 15;
            reinterpret_cast<float4*>(s_w)[idx] = *reinterpret_cast<const float4*>(
                g_w2d + (ic0 * 9 + kk) * NC + ot * 64 + c4 * 4);
        }
        __syncthreads();

#pragma unroll
        for (int cl = 0; cl < 8; cl++) {
            float aa[3][9];
#pragma unroll
            for (int ti = 0; ti < 3; ti++) {
                const float* rp = s_act + cl * 108 + (r + ti) * 12;
                float4 v0 = *reinterpret_cast<const float4*>(rp);
                float4 v1 = *reinterpret_cast<const float4*>(rp + 4);
                aa[ti][0] = v0.x; aa[ti][1] = v0.y; aa[ti][2] = v0.z; aa[ti][3] = v0.w;
                aa[ti][4] = v1.x; aa[ti][5] = v1.y; aa[ti][6] = v1.z; aa[ti][7] = v1.w;
                aa[ti][8] = rp[8];
            }
#pragma unroll
            for (int ti = 0; ti < 3; ti++) {
#pragma unroll
                for (int tj = 0; tj < 3; tj++) {
                    const float2 w = *reinterpret_cast<const float2*>(
                        s_w + (cl * 9 + ti * 3 + tj) * 64 + lane * 2);
#pragma unroll
                    for (int pj = 0; pj < 7; pj++) {
                        acc0[pj] = fmaf(aa[ti][pj + tj], w.x, acc0[pj]);
                        acc1[pj] = fmaf(aa[ti][pj + tj], w.y, acc1[pj]);
                    }
                }
            }
        }
    }

    const int oc0 = ot * 64 + lane * 2;
#pragma unroll
    for (int pj = 0; pj < 7; pj++) {
        const int p = r * 7 + pj;
        g_l2part[((size_t)(b * NC + oc0) * NP + p) * 2 + ks] = acc0[pj];
        g_l2part[((size_t)(b * NC + oc0 + 1) * NP + p) * 2 + ks] = acc1[pj];
    }
}

// ---------------- kernel 3: dw 7x7 depthwise, scalar streaming-cv ----------------
// block 224 = 4 row-groups x 56 cols; thread = 14 rows x 1 col.
// Per dj: keep ww[7] in regs; stream 20 input values one at a time, each feeding
// up to 7 FMAs into the acc[14] window. Live set ~26 regs -> no spills at cap 36,
// 8 blocks/SM (87.5% occ).
__global__ void __launch_bounds__(224, 8) dw_kernel(const float* __restrict__ x,
                                                    const float* __restrict__ wdyn,
                                                    float* __restrict__ y) {
    __shared__ float xs[62 * 62];
    __shared__ float ws[49];
    const int bc = blockIdx.x;
    const int tid = threadIdx.x;

    const float* xp = x + (size_t)bc * (NH * NW);
    for (int idx = tid; idx < 62 * 62; idx += 224) {
        const int rr = idx / 62, cc = idx % 62;
        const int gr = rr - 3, gc = cc - 3;
        float v = 0.f;
        if ((unsigned)gr < 56u && (unsigned)gc < 56u) v = xp[gr * 56 + gc];
        xs[idx] = v;
    }
    if (tid < 49) {
        const int c = bc & (NC - 1);
        const float2 lp = *reinterpret_cast<const float2*>(g_l2part + ((size_t)bc * NP + tid) * 2);
        const float ld = lp.x + lp.y + g_b2d[c];
        const float s = 1.0f / (1.0f + expf(-ld));
        const float w0 = wdyn[c * NP + tid];
        const float w1 = wdyn[NC * NP + c * NP + tid];
        ws[tid] = s * w0 + (1.0f - s) * w1;
    }
    __syncthreads();

    const int cg = tid / 56;       // 0..3 -> rows cg*14 .. cg*14+13
    const int col = tid % 56;

    float acc[14];
#pragma unroll
    for (int k = 0; k < 14; k++) acc[k] = 0.f;

#pragma unroll
    for (int dj = 0; dj < 7; dj++) {
        float ww[7];
#pragma unroll
        for (int di = 0; di < 7; di++) ww[di] = ws[di * 7 + dj];
        const float* bp = xs + (cg * 14) * 62 + col + dj;
#pragma unroll
        for (int m = 0; m < 20; m++) {
            const float v = bp[m * 62];
#pragma unroll
            for (int di = 0; di < 7; di++) {
                const int k = m - di;
                if (k >= 0 && k < 14)
                    acc[k] = fmaf(v, ww[di], acc[k]);
            }
        }
    }
    float* yp = y + (size_t)bc * (NH * NW);
#pragma unroll
    for (int k = 0; k < 14; k++)
        yp[(cg * 14 + k) * 56 + col] = acc[k];
}

// ---------------- launch ----------------
extern "C" void kernel_launch(void* const* d_in, const int* in_sizes, int n_in,
                              void* d_out, int out_size) {
    const float* x     = (const float*)d_in[0];
    const float* wdyn  = (const float*)d_in[1];
    const float* w1    = (const float*)d_in[2];
    const float* gamma = (const float*)d_in[3];
    const float* beta  = (const float*)d_in[4];
    const float* w2    = (const float*)d_in[5];
    const float* b2    = (const float*)d_in[6];
    float* y = (float*)d_out;

    prep_kernel<<<POOLBLKS + WTBLKS, 416>>>(x, w1, w2, b2);
    conv1_kernel<<<dim3(NSL, NB), 224>>>();
    conv2_kernel<<<dim3(4, 2, NB), 224>>>(gamma, beta);
    dw_kernel<<<NB * NC, 224>>>(x, wdyn, y);
}